// round 15
// baseline (speedup 1.0000x reference)
#include <cuda_runtime.h>
#include <math.h>

#define NL 1200          // lines per set
#define S  5             // NUM_SAMPLES
#define NS (NL*S)        // 6000 samples per set
#define DD 128           // descriptor dim
#define HW 128           // feature map H=W
#define TOPK 10
#define GAPP 0.1f
#define NITER 38         // ceil(NL/32)
#define CW   (NL*6)      // 7200: k-major row width (6 slots per line)

typedef unsigned long long ull;

// ---------------- scratch (no allocs allowed) ----------------
__device__ float g_pts[2*NS*2];
__device__ int   g_valid[2*NS];
__device__ float g_descT[2*HW*HW*DD];  // desc transposed to (p, d) per image
__device__ float g_desc[2*NS*DD];      // normalized descriptors, sample-major
__device__ float g_desck[2][DD][CW];   // k-major, slot-padded (line*6+s)
__device__ float g_ls[NL*NL];          // line_scores (dir1)
__device__ float g_lsT[NL*NL];         // transposed copy (dir2)
__device__ int   g_topk[2*NL*TOPK];
__device__ float g_sblk[2*NL*TOPK*25]; // 5x5 blocks for NW
__device__ float g_nwout[NL*2*TOPK];
__device__ int   g_matches[2*NL];

// ---- f32x2 packed FMA helpers (each half = exact fp32 FMA) ----
__device__ __forceinline__ ull pack2(float lo, float hi) {
    ull r;
    asm("mov.b64 %0, {%1, %2};" : "=l"(r) : "f"(lo), "f"(hi));
    return r;
}
__device__ __forceinline__ float2 unpack2(ull v) {
    float2 f;
    asm("mov.b64 {%0, %1}, %2;" : "=f"(f.x), "=f"(f.y) : "l"(v));
    return f;
}
__device__ __forceinline__ void fma2(ull& acc, ull a, ull b) {
    asm("fma.rn.f32x2 %0, %1, %2, %0;" : "+l"(acc) : "l"(a), "l"(b));
}
__device__ __forceinline__ unsigned smem_u32(const void* p) {
    unsigned r;
    asm("{ .reg .u64 t; cvta.to.shared.u64 t, %1; cvt.u32.u64 %0, t; }"
        : "=r"(r) : "l"(p));
    return r;
}
__device__ __forceinline__ ull lds64(unsigned a) {
    ull r;
    asm volatile("ld.shared.b64 %0, [%1];" : "=l"(r) : "r"(a));
    return r;
}
__device__ __forceinline__ float lds32(unsigned a) {
    float r;
    asm volatile("ld.shared.f32 %0, [%1];" : "=f"(r) : "r"(a));
    return r;
}
__device__ __forceinline__ void cpasync16(unsigned s, const void* g) {
    asm volatile("cp.async.ca.shared.global [%0], [%1], 16;" :: "r"(s), "l"(g));
}
__device__ __forceinline__ void cpcommit() {
    asm volatile("cp.async.commit_group;");
}
template <int N>
__device__ __forceinline__ void cpwait() {
    asm volatile("cp.async.wait_group %0;" :: "n"(N));
}

// ---------------- 0) transpose desc (1,D,H,W) -> (H*W, D) ----------------
__global__ void k_transpose(const float* __restrict__ d1,
                            const float* __restrict__ d2) {
    __shared__ float tile[32][33];
    const float* in = blockIdx.z ? d2 : d1;
    float* out = g_descT + (size_t)blockIdx.z * (HW*HW*DD);
    int p0 = blockIdx.x * 32, d0 = blockIdx.y * 32;
    int tx = threadIdx.x, ty = threadIdx.y;   // 32 x 8
    #pragma unroll
    for (int j = 0; j < 32; j += 8)
        tile[ty + j][tx] = in[(d0 + ty + j)*(HW*HW) + p0 + tx];
    __syncthreads();
    #pragma unroll
    for (int j = 0; j < 32; j += 8)
        out[(p0 + ty + j)*DD + d0 + tx] = tile[tx][ty + j];
}

// ---------------- 1) sample line points (XLA-exact: no FMA contraction) ----------------
__global__ void k_points(const float* __restrict__ seg1,
                         const float* __restrict__ seg2) {
    int l = blockIdx.x * blockDim.x + threadIdx.x;
    if (l >= 2*NL) return;
    const float* seg = (l < NL) ? (seg1 + l*4) : (seg2 + (l-NL)*4);
    float sy = seg[0], sx = seg[1], ey = seg[2], ex = seg[3];
    float dy = __fsub_rn(ey, sy), dx = __fsub_rn(ex, sx);
    float len = __fsqrt_rn(__fadd_rn(__fmul_rn(dy, dy), __fmul_rn(dx, dx)));
    float ns = floorf(__fdiv_rn(len, 8.0f));
    ns = fminf(fmaxf(ns, 2.0f), 5.0f);
    float den = __fsub_rn(ns, 1.0f);
    float ivy = __fdiv_rn(dy, den);
    float ivx = __fdiv_rn(dx, den);
    #pragma unroll
    for (int k = 0; k < S; k++) {
        bool v = ((float)k < ns);
        float py = __fadd_rn(sy, __fmul_rn((float)k, ivy));
        float px = __fadd_rn(sx, __fmul_rn((float)k, ivx));
        g_pts[(l*S + k)*2 + 0] = v ? py : 0.0f;
        g_pts[(l*S + k)*2 + 1] = v ? px : 0.0f;
        g_valid[l*S + k] = v ? 1 : 0;
    }
}

// ---------------- 2) bilinear sampling + L2 normalize (XLA-exact, coalesced) ----------------
__global__ void k_sample() {
    int p = blockIdx.x;              // 0..2*NS-1
    int d = threadIdx.x;             // 0..127
    int set = (p < NS) ? 0 : 1;
    int ps  = p - set*NS;
    const float* img = g_descT + (size_t)set * (HW*HW*DD);
    float py = g_pts[p*2 + 0];
    float px = g_pts[p*2 + 1];
    float xn = __fsub_rn(__fdiv_rn(__fmul_rn(2.0f, px), 511.0f), 1.0f);
    float yn = __fsub_rn(__fdiv_rn(__fmul_rn(2.0f, py), 511.0f), 1.0f);
    float ix = __fdiv_rn(__fsub_rn(__fmul_rn(__fadd_rn(xn, 1.0f), 128.0f), 1.0f), 2.0f);
    float iy = __fdiv_rn(__fsub_rn(__fmul_rn(__fadd_rn(yn, 1.0f), 128.0f), 1.0f), 2.0f);
    float x0f = floorf(ix), y0f = floorf(iy);
    float wx = __fsub_rn(ix, x0f), wy = __fsub_rn(iy, y0f);
    int x0 = (int)x0f, y0 = (int)y0f;
    int x1 = x0 + 1,  y1 = y0 + 1;

    float inb00 = ((x0 >= 0) & (x0 < HW) & (y0 >= 0) & (y0 < HW)) ? 1.0f : 0.0f;
    float inb10 = ((x1 >= 0) & (x1 < HW) & (y0 >= 0) & (y0 < HW)) ? 1.0f : 0.0f;
    float inb01 = ((x0 >= 0) & (x0 < HW) & (y1 >= 0) & (y1 < HW)) ? 1.0f : 0.0f;
    float inb11 = ((x1 >= 0) & (x1 < HW) & (y1 >= 0) & (y1 < HW)) ? 1.0f : 0.0f;
    int xc0 = min(max(x0, 0), HW-1), yc0 = min(max(y0, 0), HW-1);
    int xc1 = min(max(x1, 0), HW-1), yc1 = min(max(y1, 0), HW-1);

    float g00 = __fmul_rn(img[(yc0*HW + xc0)*DD + d], inb00);
    float g10 = __fmul_rn(img[(yc0*HW + xc1)*DD + d], inb10);
    float g01 = __fmul_rn(img[(yc1*HW + xc0)*DD + d], inb01);
    float g11 = __fmul_rn(img[(yc1*HW + xc1)*DD + d], inb11);

    float omx = __fsub_rn(1.0f, wx), omy = __fsub_rn(1.0f, wy);
    float w00 = __fmul_rn(omx, omy);
    float w10 = __fmul_rn(wx,  omy);
    float w01 = __fmul_rn(omx, wy);
    float w11 = __fmul_rn(wx,  wy);

    float m0 = __fmul_rn(g00, w00);
    float m1 = __fmul_rn(g10, w10);
    float m2 = __fmul_rn(g01, w01);
    float m3 = __fmul_rn(g11, w11);
    float v = __fadd_rn(__fadd_rn(__fadd_rn(m0, m1), m2), m3);

    __shared__ float sq[DD];
    __shared__ float s_nrm;
    sq[d] = __fmul_rn(v, v);
    __syncthreads();
    if (d < 32) {
        float partial = sq[d];
        partial = __fadd_rn(partial, sq[d + 32]);
        partial = __fadd_rn(partial, sq[d + 64]);
        partial = __fadd_rn(partial, sq[d + 96]);
        #pragma unroll
        for (int off = 16; off > 0; off >>= 1) {
            float o = __shfl_down_sync(0xffffffffu, partial, off);
            partial = __fadd_rn(partial, o);
        }
        if (d == 0) s_nrm = __fsqrt_rn(partial);
    }
    __syncthreads();
    float out = __fdiv_rn(v, s_nrm);
    g_desc[p*DD + d] = out;
    // k-major, slot-padded copy (exact same fp32 values)
    g_desck[set][d][ps + ps/5] = out;
}

// ---------------- 3) fused line_scores GEMM: 2i x 2j register blocking ----------------
// 16x16 line tile, 64 threads; thread (tip,tjq) owns i-lines {2tip,2tip+1}
// and j-lines {2tjq,2tjq+1}: 4 pairs, 100 MACs/k at 112 smem-bytes/k.
#define KK  16
#define AST 96
#define NC  (DD/KK)   // 8 chunks

__global__ void __launch_bounds__(64) k_linescores() {
    __shared__ float As[2][KK*AST];
    __shared__ float Bs[2][KK*AST];
    __shared__ char  Av[80], Bv[80];

    int tid = threadIdx.x;           // 0..63
    int tip = tid >> 3;              // 0..7 (i-pair)
    int tjq = tid & 7;               // 0..7 (j-pair)
    int i0 = blockIdx.y * 16;
    int j0 = blockIdx.x * 16;

    for (int idx = tid; idx < 80; idx += 64) {
        Av[idx] = (char)g_valid[i0*S + idx];
        Bv[idx] = (char)g_valid[NS + j0*S + idx];
    }

    const float* Asrc = &g_desck[0][0][i0*6];
    const float* Bsrc = &g_desck[1][0][j0*6];
    unsigned aSm = smem_u32(As), bSm = smem_u32(Bs);

    #define FILL(chunk, buf)                                                   \
    {                                                                          \
        int kk_ = (chunk)*KK;                                                  \
        for (int idx = tid; idx < KK*24; idx += 64) {                          \
            int r = idx / 24, c4 = idx % 24;                                   \
            unsigned da = aSm + ((buf)*KK*AST + r*AST + c4*4)*4;               \
            unsigned db = bSm + ((buf)*KK*AST + r*AST + c4*4)*4;               \
            cpasync16(da, Asrc + (size_t)(kk_ + r)*CW + c4*4);                 \
            cpasync16(db, Bsrc + (size_t)(kk_ + r)*CW + c4*4);                 \
        }                                                                      \
        cpcommit();                                                            \
    }

    FILL(0, 0)
    FILL(1, 1)

    // acc per (ii, jl) pair: accM[5][2] dots vs (b0,b1),(b2,b3);
    // accC[2] = (x0..x3) vs b4; acc44 scalar
    ull accM[2][2][S][2], accC[2][2][2];
    float acc44[2][2];
    #pragma unroll
    for (int ii = 0; ii < 2; ii++)
        #pragma unroll
        for (int jl = 0; jl < 2; jl++) {
            #pragma unroll
            for (int x = 0; x < S; x++) { accM[ii][jl][x][0] = 0ull; accM[ii][jl][x][1] = 0ull; }
            accC[ii][jl][0] = 0ull; accC[ii][jl][1] = 0ull;
            acc44[ii][jl] = 0.0f;
        }

    unsigned aBase0 = aSm + (12*tip)*4;   // 2 i-lines x 6 slots
    unsigned bBase0 = bSm + (12*tjq)*4;

    #pragma unroll
    for (int c = 0; c < NC; c++) {
        int buf = c & 1;
        if (c < NC - 1) cpwait<1>(); else cpwait<0>();
        __syncthreads();

        unsigned aBase = aBase0 + buf*(KK*AST*4);
        unsigned bBase = bBase0 + buf*(KK*AST*4);
        #pragma unroll
        for (int k = 0; k < KK; k++) {
            unsigned ao = aBase + k*(AST*4);
            unsigned bo = bBase + k*(AST*4);

            float a[2][S];
            ull ad[2][S], ap01[2], ap23[2];
            #pragma unroll
            for (int ii = 0; ii < 2; ii++) {
                unsigned av = ao + ii*24;
                a[ii][0] = lds32(av);    a[ii][1] = lds32(av+4);
                a[ii][2] = lds32(av+8);  a[ii][3] = lds32(av+12);
                a[ii][4] = lds32(av+16);
                #pragma unroll
                for (int x = 0; x < S; x++) ad[ii][x] = pack2(a[ii][x], a[ii][x]);
                ap01[ii] = pack2(a[ii][0], a[ii][1]);
                ap23[ii] = pack2(a[ii][2], a[ii][3]);
            }

            #pragma unroll
            for (int jl = 0; jl < 2; jl++) {
                unsigned bj = bo + jl*24;
                ull bp01 = lds64(bj);
                ull bp23 = lds64(bj+8);
                float b4 = lds32(bj+16);
                ull b4d = pack2(b4, b4);

                #pragma unroll
                for (int ii = 0; ii < 2; ii++) {
                    fma2(accM[ii][jl][0][0], ad[ii][0], bp01); fma2(accM[ii][jl][0][1], ad[ii][0], bp23);
                    fma2(accM[ii][jl][1][0], ad[ii][1], bp01); fma2(accM[ii][jl][1][1], ad[ii][1], bp23);
                    fma2(accM[ii][jl][2][0], ad[ii][2], bp01); fma2(accM[ii][jl][2][1], ad[ii][2], bp23);
                    fma2(accM[ii][jl][3][0], ad[ii][3], bp01); fma2(accM[ii][jl][3][1], ad[ii][3], bp23);
                    fma2(accM[ii][jl][4][0], ad[ii][4], bp01); fma2(accM[ii][jl][4][1], ad[ii][4], bp23);
                    fma2(accC[ii][jl][0], ap01[ii], b4d);
                    fma2(accC[ii][jl][1], ap23[ii], b4d);
                    acc44[ii][jl] = __fmaf_rn(a[ii][4], b4, acc44[ii][jl]);
                }
            }
        }
        __syncthreads();
        if (c + 2 < NC) FILL(c + 2, buf)
    }
    #undef FILL

    #pragma unroll
    for (int ii = 0; ii < 2; ii++) {
        int iloc = 2*tip + ii;
        bool va[S];
        #pragma unroll
        for (int r = 0; r < S; r++) va[r] = Av[iloc*S + r] != 0;

        #pragma unroll
        for (int jl = 0; jl < 2; jl++) {
            int jloc = 2*tjq + jl;
            float acc[S][S];
            #pragma unroll
            for (int x = 0; x < S; x++) {
                float2 p01 = unpack2(accM[ii][jl][x][0]);
                float2 p23 = unpack2(accM[ii][jl][x][1]);
                acc[x][0] = p01.x; acc[x][1] = p01.y;
                acc[x][2] = p23.x; acc[x][3] = p23.y;
            }
            { float2 c0 = unpack2(accC[ii][jl][0]); acc[0][4] = c0.x; acc[1][4] = c0.y; }
            { float2 c1 = unpack2(accC[ii][jl][1]); acc[2][4] = c1.x; acc[3][4] = c1.y; }
            acc[4][4] = acc44[ii][jl];

            bool vb[S];
            #pragma unroll
            for (int r = 0; r < S; r++) vb[r] = Bv[jloc*S + r] != 0;

            float blk[S][S];
            #pragma unroll
            for (int a = 0; a < S; a++)
                #pragma unroll
                for (int b = 0; b < S; b++)
                    blk[a][b] = (va[a] && vb[b]) ? acc[a][b] : -1.0f;

            float s1 = 0.0f, c1 = 0.0f, s2 = 0.0f, c2 = 0.0f;
            #pragma unroll
            for (int a = 0; a < S; a++) {
                float m = -INFINITY;
                #pragma unroll
                for (int b = 0; b < S; b++) m = fmaxf(m, blk[a][b]);
                if (m != -1.0f) { s1 = __fadd_rn(s1, m); c1 = __fadd_rn(c1, 1.0f); }
            }
            #pragma unroll
            for (int b = 0; b < S; b++) {
                float m = -INFINITY;
                #pragma unroll
                for (int a = 0; a < S; a++) m = fmaxf(m, blk[a][b]);
                if (m != -1.0f) { s2 = __fadd_rn(s2, m); c2 = __fadd_rn(c2, 1.0f); }
            }
            float ls = __fdiv_rn(__fadd_rn(__fdiv_rn(s1, c1), __fdiv_rn(s2, c2)), 2.0f);
            int gi = i0 + iloc, gj = j0 + jloc;
            g_ls [gi*NL + gj] = ls;
            g_lsT[gj*NL + gi] = ls;
        }
    }
}

// ---------------- 4) top-K: warp per row, 4 independent ILP chains ----------------
__global__ void k_topk() {
    int gwarp = (blockIdx.x * blockDim.x + threadIdx.x) >> 5;
    int lane  = threadIdx.x & 31;
    if (gwarp >= 2*NL) return;
    int dir = gwarp / NL, row = gwarp % NL;
    const float* src = dir ? &g_lsT[row*NL] : &g_ls[row*NL];

    float vals[NITER];
    #pragma unroll
    for (int i = 0; i < NITER; i++) {
        int j = lane + i*32;
        vals[i] = (j < NL) ? src[j] : -INFINITY;
    }

    float pv = INFINITY; int pj = 0x7fffffff;
    int* outp = &g_topk[dir*NL*TOPK + row*TOPK];

    for (int t = 0; t < TOPK; t++) {
        float cv[4]; int cj[4];
        #pragma unroll
        for (int ch = 0; ch < 4; ch++) { cv[ch] = -INFINITY; cj[ch] = -1; }
        #pragma unroll
        for (int i = 0; i < NITER; i++) {
            int ch = i & 3;
            int j = lane + i*32;
            float v = vals[i];
            bool elig = (v < pv) || (v == pv && j < pj);
            bool better = (v > cv[ch]) || (v == cv[ch] && j > cj[ch]);
            if (elig && better) { cv[ch] = v; cj[ch] = j; }
        }
        float bv = cv[0]; int bj = cj[0];
        #pragma unroll
        for (int ch = 1; ch < 4; ch++)
            if (cv[ch] > bv || (cv[ch] == bv && cj[ch] > bj)) { bv = cv[ch]; bj = cj[ch]; }

        #pragma unroll
        for (int off = 16; off > 0; off >>= 1) {
            float ov = __shfl_down_sync(0xffffffffu, bv, off);
            int   oj = __shfl_down_sync(0xffffffffu, bj, off);
            if (ov > bv || (ov == bv && oj > bj)) { bv = ov; bj = oj; }
        }
        bv = __shfl_sync(0xffffffffu, bv, 0);
        bj = __shfl_sync(0xffffffffu, bj, 0);
        pv = bv; pj = bj;
        if (lane == 0) outp[TOPK - 1 - t] = bj;
    }
}

// ---------------- 5a) 5x5 blocks: block per (dir,row), smem-staged ----------------
#define QP 132   // padded row stride (floats)

__global__ void __launch_bounds__(128) k_nwdots() {
    int blk = blockIdx.x;            // 0..2*NL-1
    int dir = blk / NL, row = blk % NL;
    int tid = threadIdx.x;

    __shared__ float qsm[S*QP];
    __shared__ float osm[TOPK*S*QP];
    __shared__ int   osbase[TOPK];
    __shared__ char  qvs[S];

    int qs = dir ? (NS + row*S) : (row*S);
    const int* topk = &g_topk[dir*NL*TOPK + row*TOPK];

    for (int idx = tid; idx < S*DD; idx += 128) {
        int r = idx >> 7, c = idx & 127;
        qsm[r*QP + c] = g_desc[(qs + r)*DD + c];
    }
    if (tid < S) qvs[tid] = (char)(g_valid[qs + tid] != 0);
    if (tid < TOPK) {
        int l = topk[tid];
        osbase[tid] = dir ? (l*S) : (NS + l*S);
    }
    __syncthreads();

    #pragma unroll
    for (int t = 0; t < TOPK; t++) {
        int os = osbase[t];
        for (int idx = tid; idx < S*DD; idx += 128) {
            int r = idx >> 7, c = idx & 127;
            osm[(t*S + r)*QP + c] = g_desc[(os + r)*DD + c];
        }
    }
    __syncthreads();

    for (int dd = tid; dd < TOPK*25; dd += 128) {
        int t = dd / 25, ab = dd % 25;
        int a = ab / 5, b = ab % 5;
        const float* qp = &qsm[a*QP];
        const float* op = &osm[(t*S + b)*QP];
        float acc = 0.0f;
        #pragma unroll 16
        for (int k = 0; k < DD; k++)
            acc = __fmaf_rn(qp[k], op[k], acc);
        bool valid = qvs[a] && (g_valid[osbase[t] + b] != 0);
        g_sblk[(blk*TOPK + t)*25 + ab] = valid ? acc : -1.0f;
    }
}

// ---------------- 5b) NW DP + argmax: warp per (dir,row), lane per variant ----------------
__global__ void k_nwdp() {
    int gw = (blockIdx.x * blockDim.x + threadIdx.x) >> 5;
    int lane = threadIdx.x & 31;
    if (gw >= 2*NL) return;
    int dir = gw / NL, row = gw % NL;

    float nwv = -INFINITY;
    if (lane < 2*TOPK) {
        int tt = (lane < TOPK) ? lane : (lane - TOPK);
        bool flip = lane >= TOPK;
        const float* sb = &g_sblk[((dir*NL + row)*TOPK + tt)*25];
        float s[25];
        #pragma unroll
        for (int a = 0; a < 5; a++)
            #pragma unroll
            for (int b = 0; b < 5; b++)
                s[a*5 + b] = sb[a*5 + (flip ? (4 - b) : b)];

        float prev[6] = {0,0,0,0,0,0};
        #pragma unroll
        for (int a = 0; a < S; a++) {
            float nr[6]; nr[0] = 0.0f;
            float left = 0.0f;
            #pragma unroll
            for (int b = 0; b < S; b++) {
                float sc = __fsub_rn(s[a*5 + b], GAPP);
                float cur = fmaxf(fmaxf(left, prev[b+1]), __fadd_rn(prev[b], sc));
                nr[b+1] = cur; left = cur;
            }
            #pragma unroll
            for (int b = 0; b < 6; b++) prev[b] = nr[b];
        }
        nwv = prev[5];
    }

    float bv = nwv; int bi = (lane < 2*TOPK) ? lane : (1 << 30);
    #pragma unroll
    for (int off = 16; off > 0; off >>= 1) {
        float ov = __shfl_down_sync(0xffffffffu, bv, off);
        int   oi = __shfl_down_sync(0xffffffffu, bi, off);
        if (ov > bv || (ov == bv && oi < bi)) { bv = ov; bi = oi; }
    }
    bi = __shfl_sync(0xffffffffu, bi, 0);
    if (lane == 0)
        g_matches[dir*NL + row] = g_topk[dir*NL*TOPK + row*TOPK + (bi % TOPK)];
    if (dir == 0 && lane < 2*TOPK)
        g_nwout[row*2*TOPK + lane] = nwv;
}

// ---------------- 6) mutual check + write output ----------------
__global__ void k_final(float* __restrict__ out, int out_size) {
    int i = blockIdx.x * blockDim.x + threadIdx.x;
    if (i >= NL) return;
    int m1 = g_matches[i];
    int m2 = g_matches[NL + m1];
    int res = (m2 == i) ? m1 : -1;

    if (out_size >= NL + NL*2*TOPK) {
        out[i] = (float)res;
        for (int t = 0; t < 2*TOPK; t++)
            out[NL + i*2*TOPK + t] = g_nwout[i*2*TOPK + t];
    } else if (out_size == NL*2*TOPK) {
        for (int t = 0; t < 2*TOPK; t++)
            out[i*2*TOPK + t] = g_nwout[i*2*TOPK + t];
    } else {
        out[i] = (float)res;
    }
}

// ---------------- launch ----------------
extern "C" void kernel_launch(void* const* d_in, const int* in_sizes, int n_in,
                              void* d_out, int out_size) {
    (void)in_sizes; (void)n_in;
    const float* seg1  = (const float*)d_in[0];
    const float* seg2  = (const float*)d_in[1];
    const float* desc1 = (const float*)d_in[2];
    const float* desc2 = (const float*)d_in[3];

    k_transpose<<<dim3(HW*HW/32, DD/32, 2), dim3(32, 8)>>>(desc1, desc2);
    k_points<<<(2*NL + 255)/256, 256>>>(seg1, seg2);
    k_sample<<<2*NS, DD>>>();
    k_linescores<<<dim3(NL/16, NL/16), 64>>>();
    k_topk<<<(2*NL*32 + 255)/256, 256>>>();
    k_nwdots<<<2*NL, 128>>>();
    k_nwdp<<<(2*NL*32 + 255)/256, 256>>>();
    k_final<<<(NL + 255)/256, 256>>>((float*)d_out, out_size);
}

// round 17
// speedup vs baseline: 1.7717x; 1.7717x over previous
#include <cuda_runtime.h>
#include <math.h>

#define NL 1200          // lines per set
#define S  5             // NUM_SAMPLES
#define NS (NL*S)        // 6000 samples per set
#define DD 128           // descriptor dim
#define HW 128           // feature map H=W
#define TOPK 10
#define GAPP 0.1f
#define NITER 38         // ceil(NL/32)
#define CW   (NL*6)      // 7200: k-major row width (6 slots per line)

typedef unsigned long long ull;

// ---------------- scratch (no allocs allowed) ----------------
__device__ int   g_valid[2*NS];
__device__ float g_descT[2*HW*HW*DD];  // desc transposed to (p, d) per image
__device__ float g_desc[2*NS*DD];      // normalized descriptors, sample-major
__device__ float g_desck[2][DD][CW];   // k-major, slot-padded (line*6+s)
__device__ float g_ls[NL*NL];          // line_scores (dir1)
__device__ float g_lsT[NL*NL];         // transposed copy (dir2)
__device__ int   g_topk[2*NL*TOPK];
__device__ float g_sblk[2*NL*TOPK*25]; // 5x5 blocks for NW
__device__ float g_nwout[NL*2*TOPK];
__device__ int   g_matches[2*NL];

// ---- f32x2 packed FMA helpers (each half = exact fp32 FMA) ----
__device__ __forceinline__ ull pack2(float lo, float hi) {
    ull r;
    asm("mov.b64 %0, {%1, %2};" : "=l"(r) : "f"(lo), "f"(hi));
    return r;
}
__device__ __forceinline__ float2 unpack2(ull v) {
    float2 f;
    asm("mov.b64 {%0, %1}, %2;" : "=f"(f.x), "=f"(f.y) : "l"(v));
    return f;
}
__device__ __forceinline__ void fma2(ull& acc, ull a, ull b) {
    asm("fma.rn.f32x2 %0, %1, %2, %0;" : "+l"(acc) : "l"(a), "l"(b));
}
__device__ __forceinline__ unsigned smem_u32(const void* p) {
    unsigned r;
    asm("{ .reg .u64 t; cvta.to.shared.u64 t, %1; cvt.u32.u64 %0, t; }"
        : "=r"(r) : "l"(p));
    return r;
}
__device__ __forceinline__ ull lds64(unsigned a) {
    ull r;
    asm volatile("ld.shared.b64 %0, [%1];" : "=l"(r) : "r"(a));
    return r;
}
__device__ __forceinline__ float lds32(unsigned a) {
    float r;
    asm volatile("ld.shared.f32 %0, [%1];" : "=f"(r) : "r"(a));
    return r;
}
__device__ __forceinline__ void cpasync16(unsigned s, const void* g) {
    asm volatile("cp.async.ca.shared.global [%0], [%1], 16;" :: "r"(s), "l"(g));
}
__device__ __forceinline__ void cpcommit() {
    asm volatile("cp.async.commit_group;");
}
template <int N>
__device__ __forceinline__ void cpwait() {
    asm volatile("cp.async.wait_group %0;" :: "n"(N));
}

// ---------------- 0) transpose desc (1,D,H,W) -> (H*W, D) ----------------
__global__ void k_transpose(const float* __restrict__ d1,
                            const float* __restrict__ d2) {
    __shared__ float tile[32][33];
    const float* in = blockIdx.z ? d2 : d1;
    float* out = g_descT + (size_t)blockIdx.z * (HW*HW*DD);
    int p0 = blockIdx.x * 32, d0 = blockIdx.y * 32;
    int tx = threadIdx.x, ty = threadIdx.y;   // 32 x 8
    #pragma unroll
    for (int j = 0; j < 32; j += 8)
        tile[ty + j][tx] = in[(d0 + ty + j)*(HW*HW) + p0 + tx];
    __syncthreads();
    #pragma unroll
    for (int j = 0; j < 32; j += 8)
        out[(p0 + ty + j)*DD + d0 + tx] = tile[tx][ty + j];
}

// ---------------- 1+2) fused point sampling + bilinear + L2 norm ----------------
// One warp per point. XLA norm partial for lane t is sq[t]+sq[t+32]+sq[t+64]+sq[t+96]
// (lane-strided) -> computed natively; same left-assoc order, same shfl tree.
__global__ void __launch_bounds__(256) k_sample(const float* __restrict__ seg1,
                                                const float* __restrict__ seg2) {
    int p    = (blockIdx.x * blockDim.x + threadIdx.x) >> 5;
    int lane = threadIdx.x & 31;
    if (p >= 2*NS) return;
    int set = (p < NS) ? 0 : 1;
    int ps  = p - set*NS;
    int line = ps / 5, kk = ps % 5;

    // ---- point (XLA-exact, no FMA contraction) ----
    const float* seg = set ? (seg2 + line*4) : (seg1 + line*4);
    float sy = seg[0], sx = seg[1], ey = seg[2], ex = seg[3];
    float dy = __fsub_rn(ey, sy), dx = __fsub_rn(ex, sx);
    float len = __fsqrt_rn(__fadd_rn(__fmul_rn(dy, dy), __fmul_rn(dx, dx)));
    float ns = floorf(__fdiv_rn(len, 8.0f));
    ns = fminf(fmaxf(ns, 2.0f), 5.0f);
    float den = __fsub_rn(ns, 1.0f);
    bool vld = ((float)kk < ns);
    float py = vld ? __fadd_rn(sy, __fmul_rn((float)kk, __fdiv_rn(dy, den))) : 0.0f;
    float px = vld ? __fadd_rn(sx, __fmul_rn((float)kk, __fdiv_rn(dx, den))) : 0.0f;
    if (lane == 0) g_valid[p] = vld ? 1 : 0;

    // ---- bilinear coords (XLA-exact) ----
    float xn = __fsub_rn(__fdiv_rn(__fmul_rn(2.0f, px), 511.0f), 1.0f);
    float yn = __fsub_rn(__fdiv_rn(__fmul_rn(2.0f, py), 511.0f), 1.0f);
    float ix = __fdiv_rn(__fsub_rn(__fmul_rn(__fadd_rn(xn, 1.0f), 128.0f), 1.0f), 2.0f);
    float iy = __fdiv_rn(__fsub_rn(__fmul_rn(__fadd_rn(yn, 1.0f), 128.0f), 1.0f), 2.0f);
    float x0f = floorf(ix), y0f = floorf(iy);
    float wx = __fsub_rn(ix, x0f), wy = __fsub_rn(iy, y0f);
    int x0 = (int)x0f, y0 = (int)y0f;
    int x1 = x0 + 1,  y1 = y0 + 1;

    float inb00 = ((x0 >= 0) & (x0 < HW) & (y0 >= 0) & (y0 < HW)) ? 1.0f : 0.0f;
    float inb10 = ((x1 >= 0) & (x1 < HW) & (y0 >= 0) & (y0 < HW)) ? 1.0f : 0.0f;
    float inb01 = ((x0 >= 0) & (x0 < HW) & (y1 >= 0) & (y1 < HW)) ? 1.0f : 0.0f;
    float inb11 = ((x1 >= 0) & (x1 < HW) & (y1 >= 0) & (y1 < HW)) ? 1.0f : 0.0f;
    int xc0 = min(max(x0, 0), HW-1), yc0 = min(max(y0, 0), HW-1);
    int xc1 = min(max(x1, 0), HW-1), yc1 = min(max(y1, 0), HW-1);

    float omx = __fsub_rn(1.0f, wx), omy = __fsub_rn(1.0f, wy);
    float w00 = __fmul_rn(omx, omy);
    float w10 = __fmul_rn(wx,  omy);
    float w01 = __fmul_rn(omx, wy);
    float w11 = __fmul_rn(wx,  wy);

    const float* img = g_descT + (size_t)set * (HW*HW*DD);
    const float* i00 = img + (yc0*HW + xc0)*DD;
    const float* i10 = img + (yc0*HW + xc1)*DD;
    const float* i01 = img + (yc1*HW + xc0)*DD;
    const float* i11 = img + (yc1*HW + xc1)*DD;

    float v[4];
    float partial = 0.0f;
    #pragma unroll
    for (int q = 0; q < 4; q++) {
        int d = lane + q*32;
        float g00 = __fmul_rn(i00[d], inb00);
        float g10 = __fmul_rn(i10[d], inb10);
        float g01 = __fmul_rn(i01[d], inb01);
        float g11 = __fmul_rn(i11[d], inb11);
        float m0 = __fmul_rn(g00, w00);
        float m1 = __fmul_rn(g10, w10);
        float m2 = __fmul_rn(g01, w01);
        float m3 = __fmul_rn(g11, w11);
        float vv = __fadd_rn(__fadd_rn(__fadd_rn(m0, m1), m2), m3);
        v[q] = vv;
        float sq = __fmul_rn(vv, vv);
        partial = (q == 0) ? sq : __fadd_rn(partial, sq);
    }
    #pragma unroll
    for (int off = 16; off > 0; off >>= 1) {
        float o = __shfl_down_sync(0xffffffffu, partial, off);
        partial = __fadd_rn(partial, o);
    }
    float total = __shfl_sync(0xffffffffu, partial, 0);
    float nrm = __fsqrt_rn(total);

    int slot = ps + ps/5;
    #pragma unroll
    for (int q = 0; q < 4; q++) {
        int d = lane + q*32;
        float out = __fdiv_rn(v[q], nrm);
        g_desc[p*DD + d] = out;
        g_desck[set][d][slot] = out;
    }
}

// ---------------- 3) fused line_scores GEMM (best measured version) ----------------
#define KK  32
#define AST 96
#define NC  (DD/KK)   // 4 chunks

__global__ void __launch_bounds__(128) k_linescores() {
    __shared__ float As[2][KK*AST];
    __shared__ float Bs[2][KK*AST];
    __shared__ char  Av[80], Bv[80];

    int tid = threadIdx.x;           // 0..127
    int ti  = tid >> 3;              // 0..15
    int tjq = tid & 7;               // 0..7 (j-pair)
    int i0 = blockIdx.y * 16;
    int j0 = blockIdx.x * 16;

    if (tid < 80) {
        Av[tid] = (char)g_valid[i0*S + tid];
        Bv[tid] = (char)g_valid[NS + j0*S + tid];
    }

    const float* Asrc = &g_desck[0][0][i0*6];
    const float* Bsrc = &g_desck[1][0][j0*6];
    unsigned aSm = smem_u32(As), bSm = smem_u32(Bs);

    #define FILL(chunk, buf)                                                   \
    {                                                                          \
        int kk_ = (chunk)*KK;                                                  \
        for (int idx = tid; idx < KK*24; idx += 128) {                         \
            int r = idx / 24, c4 = idx % 24;                                   \
            unsigned da = aSm + ((buf)*KK*AST + r*AST + c4*4)*4;               \
            unsigned db = bSm + ((buf)*KK*AST + r*AST + c4*4)*4;               \
            cpasync16(da, Asrc + (size_t)(kk_ + r)*CW + c4*4);                 \
            cpasync16(db, Bsrc + (size_t)(kk_ + r)*CW + c4*4);                 \
        }                                                                      \
        cpcommit();                                                            \
    }

    FILL(0, 0)
    FILL(1, 1)

    ull accM[2][S][2], accC[2][2];
    float acc44[2];
    #pragma unroll
    for (int jl = 0; jl < 2; jl++) {
        #pragma unroll
        for (int x = 0; x < S; x++) { accM[jl][x][0] = 0ull; accM[jl][x][1] = 0ull; }
        accC[jl][0] = 0ull; accC[jl][1] = 0ull;
        acc44[jl] = 0.0f;
    }

    unsigned aBase0 = aSm + (6*ti)*4;
    unsigned bBase0 = bSm + (6*(2*tjq))*4;

    #pragma unroll
    for (int c = 0; c < NC; c++) {
        int buf = c & 1;
        if (c < NC - 1) cpwait<1>(); else cpwait<0>();
        __syncthreads();

        unsigned aBase = aBase0 + buf*(KK*AST*4);
        unsigned bBase = bBase0 + buf*(KK*AST*4);
        #pragma unroll 8
        for (int k = 0; k < KK; k++) {
            unsigned ao = aBase + k*(AST*4);
            unsigned bo = bBase + k*(AST*4);
            float a0 = lds32(ao), a1 = lds32(ao+4), a2 = lds32(ao+8),
                  a3 = lds32(ao+12), a4 = lds32(ao+16);
            ull ad0 = pack2(a0,a0), ad1 = pack2(a1,a1), ad2 = pack2(a2,a2),
                ad3 = pack2(a3,a3), ad4 = pack2(a4,a4);
            ull ap01 = pack2(a0,a1), ap23 = pack2(a2,a3);

            #pragma unroll
            for (int jl = 0; jl < 2; jl++) {
                unsigned bj = bo + jl*24;
                ull bp01 = lds64(bj);
                ull bp23 = lds64(bj+8);
                float b4 = lds32(bj+16);
                ull b4d = pack2(b4,b4);

                fma2(accM[jl][0][0], ad0, bp01); fma2(accM[jl][0][1], ad0, bp23);
                fma2(accM[jl][1][0], ad1, bp01); fma2(accM[jl][1][1], ad1, bp23);
                fma2(accM[jl][2][0], ad2, bp01); fma2(accM[jl][2][1], ad2, bp23);
                fma2(accM[jl][3][0], ad3, bp01); fma2(accM[jl][3][1], ad3, bp23);
                fma2(accM[jl][4][0], ad4, bp01); fma2(accM[jl][4][1], ad4, bp23);
                fma2(accC[jl][0], ap01, b4d);
                fma2(accC[jl][1], ap23, b4d);
                acc44[jl] = __fmaf_rn(a4, b4, acc44[jl]);
            }
        }
        __syncthreads();
        if (c + 2 < NC) FILL(c + 2, buf)
    }
    #undef FILL

    bool va[S];
    #pragma unroll
    for (int r = 0; r < S; r++) va[r] = Av[ti*S + r] != 0;

    #pragma unroll
    for (int jl = 0; jl < 2; jl++) {
        int jloc = 2*tjq + jl;
        float acc[S][S];
        #pragma unroll
        for (int x = 0; x < S; x++) {
            float2 p01 = unpack2(accM[jl][x][0]);
            float2 p23 = unpack2(accM[jl][x][1]);
            acc[x][0] = p01.x; acc[x][1] = p01.y;
            acc[x][2] = p23.x; acc[x][3] = p23.y;
        }
        { float2 c0 = unpack2(accC[jl][0]); acc[0][4] = c0.x; acc[1][4] = c0.y; }
        { float2 c1 = unpack2(accC[jl][1]); acc[2][4] = c1.x; acc[3][4] = c1.y; }
        acc[4][4] = acc44[jl];

        bool vb[S];
        #pragma unroll
        for (int r = 0; r < S; r++) vb[r] = Bv[jloc*S + r] != 0;

        float blk[S][S];
        #pragma unroll
        for (int a = 0; a < S; a++)
            #pragma unroll
            for (int b = 0; b < S; b++)
                blk[a][b] = (va[a] && vb[b]) ? acc[a][b] : -1.0f;

        float s1 = 0.0f, c1 = 0.0f, s2 = 0.0f, c2 = 0.0f;
        #pragma unroll
        for (int a = 0; a < S; a++) {
            float m = -INFINITY;
            #pragma unroll
            for (int b = 0; b < S; b++) m = fmaxf(m, blk[a][b]);
            if (m != -1.0f) { s1 = __fadd_rn(s1, m); c1 = __fadd_rn(c1, 1.0f); }
        }
        #pragma unroll
        for (int b = 0; b < S; b++) {
            float m = -INFINITY;
            #pragma unroll
            for (int a = 0; a < S; a++) m = fmaxf(m, blk[a][b]);
            if (m != -1.0f) { s2 = __fadd_rn(s2, m); c2 = __fadd_rn(c2, 1.0f); }
        }
        float ls = __fdiv_rn(__fadd_rn(__fdiv_rn(s1, c1), __fdiv_rn(s2, c2)), 2.0f);
        int gi = i0 + ti, gj = j0 + jloc;
        g_ls [gi*NL + gj] = ls;
        g_lsT[gj*NL + gi] = ls;
    }
}

// ---------------- 4) top-K: warp per row, 4 independent ILP chains ----------------
__global__ void k_topk() {
    int gwarp = (blockIdx.x * blockDim.x + threadIdx.x) >> 5;
    int lane  = threadIdx.x & 31;
    if (gwarp >= 2*NL) return;
    int dir = gwarp / NL, row = gwarp % NL;
    const float* src = dir ? &g_lsT[row*NL] : &g_ls[row*NL];

    float vals[NITER];
    #pragma unroll
    for (int i = 0; i < NITER; i++) {
        int j = lane + i*32;
        vals[i] = (j < NL) ? src[j] : -INFINITY;
    }

    float pv = INFINITY; int pj = 0x7fffffff;
    int* outp = &g_topk[dir*NL*TOPK + row*TOPK];

    for (int t = 0; t < TOPK; t++) {
        float cv[4]; int cj[4];
        #pragma unroll
        for (int ch = 0; ch < 4; ch++) { cv[ch] = -INFINITY; cj[ch] = -1; }
        #pragma unroll
        for (int i = 0; i < NITER; i++) {
            int ch = i & 3;
            int j = lane + i*32;
            float v = vals[i];
            bool elig = (v < pv) || (v == pv && j < pj);
            bool better = (v > cv[ch]) || (v == cv[ch] && j > cj[ch]);
            if (elig && better) { cv[ch] = v; cj[ch] = j; }
        }
        float bv = cv[0]; int bj = cj[0];
        #pragma unroll
        for (int ch = 1; ch < 4; ch++)
            if (cv[ch] > bv || (cv[ch] == bv && cj[ch] > bj)) { bv = cv[ch]; bj = cj[ch]; }

        #pragma unroll
        for (int off = 16; off > 0; off >>= 1) {
            float ov = __shfl_down_sync(0xffffffffu, bv, off);
            int   oj = __shfl_down_sync(0xffffffffu, bj, off);
            if (ov > bv || (ov == bv && oj > bj)) { bv = ov; bj = oj; }
        }
        bv = __shfl_sync(0xffffffffu, bv, 0);
        bj = __shfl_sync(0xffffffffu, bj, 0);
        pv = bv; pj = bj;
        if (lane == 0) outp[TOPK - 1 - t] = bj;
    }
}

// ---------------- 5a) 5x5 blocks: block per (dir,row), smem-staged ----------------
#define QP 132   // padded row stride (floats)

__global__ void __launch_bounds__(128) k_nwdots() {
    int blk = blockIdx.x;            // 0..2*NL-1
    int dir = blk / NL, row = blk % NL;
    int tid = threadIdx.x;

    __shared__ float qsm[S*QP];
    __shared__ float osm[TOPK*S*QP];
    __shared__ int   osbase[TOPK];
    __shared__ char  qvs[S];

    int qs = dir ? (NS + row*S) : (row*S);
    const int* topk = &g_topk[dir*NL*TOPK + row*TOPK];

    for (int idx = tid; idx < S*DD; idx += 128) {
        int r = idx >> 7, c = idx & 127;
        qsm[r*QP + c] = g_desc[(qs + r)*DD + c];
    }
    if (tid < S) qvs[tid] = (char)(g_valid[qs + tid] != 0);
    if (tid < TOPK) {
        int l = topk[tid];
        osbase[tid] = dir ? (l*S) : (NS + l*S);
    }
    __syncthreads();

    #pragma unroll
    for (int t = 0; t < TOPK; t++) {
        int os = osbase[t];
        for (int idx = tid; idx < S*DD; idx += 128) {
            int r = idx >> 7, c = idx & 127;
            osm[(t*S + r)*QP + c] = g_desc[(os + r)*DD + c];
        }
    }
    __syncthreads();

    for (int dd = tid; dd < TOPK*25; dd += 128) {
        int t = dd / 25, ab = dd % 25;
        int a = ab / 5, b = ab % 5;
        const float* qp = &qsm[a*QP];
        const float* op = &osm[(t*S + b)*QP];
        float acc = 0.0f;
        #pragma unroll 16
        for (int k = 0; k < DD; k++)
            acc = __fmaf_rn(qp[k], op[k], acc);
        bool valid = qvs[a] && (g_valid[osbase[t] + b] != 0);
        g_sblk[(blk*TOPK + t)*25 + ab] = valid ? acc : -1.0f;
    }
}

// ---------------- 5b) NW DP + argmax: warp per (dir,row), lane per variant ----------------
__global__ void k_nwdp() {
    int gw = (blockIdx.x * blockDim.x + threadIdx.x) >> 5;
    int lane = threadIdx.x & 31;
    if (gw >= 2*NL) return;
    int dir = gw / NL, row = gw % NL;

    float nwv = -INFINITY;
    if (lane < 2*TOPK) {
        int tt = (lane < TOPK) ? lane : (lane - TOPK);
        bool flip = lane >= TOPK;
        const float* sb = &g_sblk[((dir*NL + row)*TOPK + tt)*25];
        float s[25];
        #pragma unroll
        for (int a = 0; a < 5; a++)
            #pragma unroll
            for (int b = 0; b < 5; b++)
                s[a*5 + b] = sb[a*5 + (flip ? (4 - b) : b)];

        float prev[6] = {0,0,0,0,0,0};
        #pragma unroll
        for (int a = 0; a < S; a++) {
            float nr[6]; nr[0] = 0.0f;
            float left = 0.0f;
            #pragma unroll
            for (int b = 0; b < S; b++) {
                float sc = __fsub_rn(s[a*5 + b], GAPP);
                float cur = fmaxf(fmaxf(left, prev[b+1]), __fadd_rn(prev[b], sc));
                nr[b+1] = cur; left = cur;
            }
            #pragma unroll
            for (int b = 0; b < 6; b++) prev[b] = nr[b];
        }
        nwv = prev[5];
    }

    float bv = nwv; int bi = (lane < 2*TOPK) ? lane : (1 << 30);
    #pragma unroll
    for (int off = 16; off > 0; off >>= 1) {
        float ov = __shfl_down_sync(0xffffffffu, bv, off);
        int   oi = __shfl_down_sync(0xffffffffu, bi, off);
        if (ov > bv || (ov == bv && oi < bi)) { bv = ov; bi = oi; }
    }
    bi = __shfl_sync(0xffffffffu, bi, 0);
    if (lane == 0)
        g_matches[dir*NL + row] = g_topk[dir*NL*TOPK + row*TOPK + (bi % TOPK)];
    if (dir == 0 && lane < 2*TOPK)
        g_nwout[row*2*TOPK + lane] = nwv;
}

// ---------------- 6) mutual check + write output ----------------
__global__ void k_final(float* __restrict__ out, int out_size) {
    int i = blockIdx.x * blockDim.x + threadIdx.x;
    if (i >= NL) return;
    int m1 = g_matches[i];
    int m2 = g_matches[NL + m1];
    int res = (m2 == i) ? m1 : -1;

    if (out_size >= NL + NL*2*TOPK) {
        out[i] = (float)res;
        for (int t = 0; t < 2*TOPK; t++)
            out[NL + i*2*TOPK + t] = g_nwout[i*2*TOPK + t];
    } else if (out_size == NL*2*TOPK) {
        for (int t = 0; t < 2*TOPK; t++)
            out[i*2*TOPK + t] = g_nwout[i*2*TOPK + t];
    } else {
        out[i] = (float)res;
    }
}

// ---------------- launch ----------------
extern "C" void kernel_launch(void* const* d_in, const int* in_sizes, int n_in,
                              void* d_out, int out_size) {
    (void)in_sizes; (void)n_in;
    const float* seg1  = (const float*)d_in[0];
    const float* seg2  = (const float*)d_in[1];
    const float* desc1 = (const float*)d_in[2];
    const float* desc2 = (const float*)d_in[3];

    k_transpose<<<dim3(HW*HW/32, DD/32, 2), dim3(32, 8)>>>(desc1, desc2);
    k_sample<<<(2*NS*32 + 255)/256, 256>>>(seg1, seg2);
    k_linescores<<<dim3(NL/16, NL/16), 128>>>();
    k_topk<<<(2*NL*32 + 255)/256, 256>>>();
    k_nwdots<<<2*NL, 128>>>();
    k_nwdp<<<(2*NL*32 + 255)/256, 256>>>();
    k_final<<<(NL + 255)/256, 256>>>((float*)d_out, out_size);
}